// round 14
// baseline (speedup 1.0000x reference)
#include <cuda_runtime.h>
#include <math.h>
#define FULL 0xffffffffu

__device__ float g_M1[128*128];
__device__ float g_qstate[32*16*128];
__device__ float g_qkg[32*16*128];
__device__ float g_cq1[32*16];
__device__ float g_cq0[32*16];
__device__ float g_Tpart[32*8*16*128];
__device__ float g_t1p[32*8*16];
__device__ float g_t2p[32*8*16];
__device__ float g_rstdc[32*4096];
__device__ float g_mc[32*4096];

static __device__ __forceinline__ float dot4(float4 a, float4 b) {
    return fmaf(a.x,b.x,fmaf(a.y,b.y,fmaf(a.z,b.z,a.w*b.w)));
}
static __device__ __forceinline__ unsigned tf32r(float x){
    unsigned u; asm("cvt.rna.tf32.f32 %0, %1;" : "=r"(u) : "f"(x)); return u;
}
#define MMA1688(D,A0,A1,A2,A3,B0,B1) \
  asm volatile("mma.sync.aligned.m16n8k8.row.col.f32.tf32.tf32.f32 " \
    "{%0,%1,%2,%3},{%4,%5,%6,%7},{%8,%9},{%0,%1,%2,%3};" \
    : "+f"(D[0]),"+f"(D[1]),"+f"(D[2]),"+f"(D[3]) \
    : "r"(A0),"r"(A1),"r"(A2),"r"(A3),"r"(B0),"r"(B1))

static __device__ __forceinline__ float fexp(float x) {
    x = fmaxf(x, -87.f);
    float t = fmaf(x, 1.4426950408889634f, 12582912.f);
    int ni = __float_as_int(t) - 0x4B400000;
    float n = t - 12582912.f;
    float f = fmaf(x, 1.4426950408889634f, -n);
    float p = 1.5403530e-4f;
    p = fmaf(p,f,1.3333558e-3f); p = fmaf(p,f,9.6181291e-3f);
    p = fmaf(p,f,5.5504109e-2f); p = fmaf(p,f,2.4022651e-1f);
    p = fmaf(p,f,6.9314718e-1f); p = fmaf(p,f,1.f);
    return p * __int_as_float((ni + 127) << 23);
}

__global__ void kM1(const float* __restrict__ Wq, const float* __restrict__ Wk){
    __shared__ float wq[128];
    int e=blockIdx.x, d=threadIdx.x;
    wq[d]=Wq[d*128+e];
    __syncthreads();
    float a=0.f;
#pragma unroll 8
    for(int c=0;c<128;c++) a=fmaf(wq[c],Wk[c*128+d],a);
    g_M1[e*128+d]=a*0.08838834764831845f;
}

static __device__ __forceinline__ void ln_row(const float (*sq)[128], float (*sz)[128],
        const float* gq, const float* bq, int w, int l){
    float4 y4=((const float4*)sq[w])[l];
    float s=y4.x+y4.y+y4.z+y4.w;
    float s2=fmaf(y4.x,y4.x,fmaf(y4.y,y4.y,fmaf(y4.z,y4.z,y4.w*y4.w)));
#pragma unroll
    for(int d=16;d>0;d>>=1){s+=__shfl_xor_sync(FULL,s,d);s2+=__shfl_xor_sync(FULL,s2,d);}
    float m=s*(1.f/128.f);
    float rstd=rsqrtf(fmaf(s2,1.f/128.f,-m*m)+1e-5f);
    float4 gg=((const float4*)gq)[l], bb=((const float4*)bq)[l];
    float4 z4;
    z4.x=fmaf((y4.x-m)*rstd,gg.x,bb.x); z4.y=fmaf((y4.y-m)*rstd,gg.y,bb.y);
    z4.z=fmaf((y4.z-m)*rstd,gg.z,bb.z); z4.w=fmaf((y4.w-m)*rstd,gg.w,bb.w);
    ((float4*)sz[w])[l]=z4;
}

template<int NR>
static __device__ __forceinline__ void qkproj(const float (*sz)[128], float (*qkraw)[128],
        const float* gkv, const float* bkv, int qbase, int t, int w, int l){
    const int RG=NR/2;
    int c=t&127, rq=(t>>7)*RG;
    float acc[RG];
#pragma unroll
    for(int k=0;k<RG;k++) acc[k]=0.f;
#pragma unroll 8
    for(int e=0;e<128;e++){
        float mv=g_M1[e*128+c];
#pragma unroll
        for(int k=0;k<RG;k++) acc[k]=fmaf(sz[rq+k][e],mv,acc[k]);
    }
#pragma unroll
    for(int k=0;k<RG;k++) qkraw[rq+k][c]=acc[k];
    __syncthreads();
    if(w<NR){
        float4 qr=((const float4*)qkraw[w])[l];
        float4 g4=((const float4*)gkv)[l], b4=((const float4*)bkv)[l];
        float c1=dot4(qr,g4), c0=dot4(qr,b4);
#pragma unroll
        for(int d=16;d>0;d>>=1){c1+=__shfl_xor_sync(FULL,c1,d);c0+=__shfl_xor_sync(FULL,c0,d);}
        if(l==0){g_cq1[qbase+w]=c1; g_cq0[qbase+w]=c0;}
        float4 o; o.x=qr.x*g4.x; o.y=qr.y*g4.y; o.z=qr.z*g4.z; o.w=qr.w*g4.w;
        ((float4*)(g_qkg+(qbase+w)*128))[l]=o;
    }
}

__global__ void __launch_bounds__(256) kqk0(const float* __restrict__ query,
        const float* __restrict__ gq,
        const float* __restrict__ bq, const float* __restrict__ gkv,
        const float* __restrict__ bkv){
    int qbase=blockIdx.x*8, t=threadIdx.x, w=t>>5, l=t&31;
    __shared__ float sq[8][128], sz[8][128], qkraw[8][128];
#pragma unroll
    for(int k=0;k<4;k++){
        float v=query[qbase*128+k*256+t];
        ((float*)sq)[k*256+t]=v;
        g_qstate[qbase*128+k*256+t]=v;
    }
    __syncthreads();
    ln_row(sq,sz,gq,bq,w,l);
    __syncthreads();
    qkproj<8>(sz,qkraw,gkv,bkv,qbase,t,w,l);
}

#define STG0 0
#define QKF  16384
#define WBUF 18432
#define RSTD 20608
#define MS   21120
#define SBLK 21632
#define T1S  23680
#define T2S  23696
#define CQ1S 23712
#define CQ0S 23728
#define SMEMF 23744

// ---- single-pass stream: split-committed cp.async halves ----
__global__ void __launch_bounds__(256,2) kstream10(const float* __restrict__ inp,
        float* __restrict__ a0out, int writeA0, int iter0){
    extern __shared__ float sm[];
    int p=blockIdx.x, b=blockIdx.y, t=threadIdx.x, w=t>>5, l=t&31;
    int g=l>>2, c4=l&3;
    if(t<16){
        sm[T1S+t]=0.f; sm[T2S+t]=0.f;
        sm[CQ1S+t]=g_cq1[b*16+t]; sm[CQ0S+t]=g_cq0[b*16+t];
    }
#pragma unroll
    for(int e=0;e<8;e++){
        int gi=e*256+t;
        int j=gi&1, nt=(gi>>1)&1, lane=(gi>>2)&31, k=gi>>7;
        int slot=nt*8+(lane>>2), ch=k*8+(lane&3)+j*4;
        sm[QKF+gi]=__uint_as_float(tf32r(g_qkg[b*2048+slot*128+ch]));
    }
    if(!iter0){
#pragma unroll
        for(int k=0;k<2;k++){
            sm[RSTD+k*256+t]=g_rstdc[b*4096+p*512+k*256+t];
            sm[MS+k*256+t]=g_mc[b*4096+p*512+k*256+t];
        }
    }
    __syncthreads();
    int rb=w*64;
    if(iter0){
        const float4* base=(const float4*)(inp+((size_t)b*4096+p*512+rb)*128);
        for(int i=0;i<64;i++){
            float4 x=base[i*32+l];
            float s=x.x+x.y+x.z+x.w;
            float s2=fmaf(x.x,x.x,fmaf(x.y,x.y,fmaf(x.z,x.z,x.w*x.w)));
#pragma unroll
            for(int d=16;d>0;d>>=1){s+=__shfl_xor_sync(FULL,s,d);s2+=__shfl_xor_sync(FULL,s2,d);}
            float m=s*(1.f/128.f);
            float rs=rsqrtf(fmaf(s2,1.f/128.f,-m*m)+1e-5f);
            if(l==0){sm[RSTD+rb+i]=rs;sm[MS+rb+i]=m;}
        }
        __syncthreads();
#pragma unroll
        for(int k=0;k<2;k++){
            g_rstdc[b*4096+p*512+k*256+t]=sm[RSTD+k*256+t];
            g_mc[b*4096+p*512+k*256+t]=sm[MS+k*256+t];
        }
    }
    float cq1v[4], cq0v[4];
    {
        int s0=2*c4;
        cq1v[0]=sm[CQ1S+s0];   cq1v[1]=sm[CQ1S+s0+1];
        cq1v[2]=sm[CQ1S+s0+8]; cq1v[3]=sm[CQ1S+s0+9];
        cq0v[0]=sm[CQ0S+s0];   cq0v[1]=sm[CQ0S+s0+1];
        cq0v[2]=sm[CQ0S+s0+8]; cq0v[3]=sm[CQ0S+s0+9];
    }
    float sacc[64];
#pragma unroll
    for(int i=0;i<64;i++) sacc[i]=0.f;
    float t1p[4]={0,0,0,0}, t2p[4]={0,0,0,0};
    int wst=STG0+w*2048;
    int wb=WBUF+w*272;

    for(int tile=0;tile<4;tile++){
        __syncwarp();
        int rb16=rb+tile*16;
        const float4* gsrc=(const float4*)(inp+((size_t)b*4096+p*512+rb16)*128);
        // stage halves with separate commits
#pragma unroll
        for(int half=0;half<2;half++){
#pragma unroll
            for(int ii=0;ii<8;ii++){
                int row=ii*2+(l>>4);
                const float4* src=gsrc+row*32+half*16+(l&15);
                unsigned dst=(unsigned)__cvta_generic_to_shared(
                    sm+wst+half*1024+row*64+(((l&15)*4)^((row&7)<<2)));
                asm volatile("cp.async.cg.shared.global [%0], [%1], 16;\n"
                             ::"r"(dst),"l"(src):"memory");
            }
            asm volatile("cp.async.commit_group;\n":::"memory");
        }
        float d0[4]={0,0,0,0}, d1[4]={0,0,0,0};
        int abase=wst+g*64;
        // half 0 compute overlapped with half 1 load
        asm volatile("cp.async.wait_group 1;\n":::"memory");
        __syncwarp();
#pragma unroll
        for(int kk=0;kk<8;kk++){
            int x0=((kk*8)+c4)^(g<<2);
            unsigned a0=__float_as_uint(sm[abase+x0]);
            unsigned a1=__float_as_uint(sm[abase+512+x0]);
            unsigned a2=__float_as_uint(sm[abase+(x0^4)]);
            unsigned a3=__float_as_uint(sm[abase+512+(x0^4)]);
            float4 bv=*(const float4*)&sm[QKF+kk*128+l*4];
            MMA1688(d0,a0,a1,a2,a3,__float_as_uint(bv.x),__float_as_uint(bv.y));
            MMA1688(d1,a0,a1,a2,a3,__float_as_uint(bv.z),__float_as_uint(bv.w));
        }
        asm volatile("cp.async.wait_group 0;\n":::"memory");
        __syncwarp();
#pragma unroll
        for(int kk=0;kk<8;kk++){
            int ab=abase+1024;
            int x0=((kk*8)+c4)^(g<<2);
            unsigned a0=__float_as_uint(sm[ab+x0]);
            unsigned a1=__float_as_uint(sm[ab+512+x0]);
            unsigned a2=__float_as_uint(sm[ab+(x0^4)]);
            unsigned a3=__float_as_uint(sm[ab+512+(x0^4)]);
            float4 bv=*(const float4*)&sm[QKF+(kk+8)*128+l*4];
            MMA1688(d0,a0,a1,a2,a3,__float_as_uint(bv.x),__float_as_uint(bv.y));
            MMA1688(d1,a0,a1,a2,a3,__float_as_uint(bv.z),__float_as_uint(bv.w));
        }
        int r0g=rb16+g, r1g=r0g+8;
        float rs0=sm[RSTD+r0g], m0=sm[MS+r0g];
        float rs1=sm[RSTD+r1g], m1=sm[MS+r1g];
        float Lg[4], Lh[4];
        Lg[0]=fmaf(rs0,fmaf(-m0,cq1v[0],d0[0]),cq0v[0]);
        Lg[1]=fmaf(rs0,fmaf(-m0,cq1v[1],d0[1]),cq0v[1]);
        Lg[2]=fmaf(rs0,fmaf(-m0,cq1v[2],d1[0]),cq0v[2]);
        Lg[3]=fmaf(rs0,fmaf(-m0,cq1v[3],d1[1]),cq0v[3]);
        Lh[0]=fmaf(rs1,fmaf(-m1,cq1v[0],d0[2]),cq0v[0]);
        Lh[1]=fmaf(rs1,fmaf(-m1,cq1v[1],d0[3]),cq0v[1]);
        Lh[2]=fmaf(rs1,fmaf(-m1,cq1v[2],d1[2]),cq0v[2]);
        Lh[3]=fmaf(rs1,fmaf(-m1,cq1v[3],d1[3]),cq0v[3]);
        float mx0=fmaxf(fmaxf(Lg[0],Lg[1]),fmaxf(Lg[2],Lg[3]));
        float mx1=fmaxf(fmaxf(Lh[0],Lh[1]),fmaxf(Lh[2],Lh[3]));
        mx0=fmaxf(mx0,__shfl_xor_sync(FULL,mx0,1));
        mx0=fmaxf(mx0,__shfl_xor_sync(FULL,mx0,2));
        mx1=fmaxf(mx1,__shfl_xor_sync(FULL,mx1,1));
        mx1=fmaxf(mx1,__shfl_xor_sync(FULL,mx1,2));
        float ag[4], ah[4], sum0=0.f, sum1=0.f;
#pragma unroll
        for(int j=0;j<4;j++){
            ag[j]=fexp(Lg[j]-mx0); sum0+=ag[j];
            ah[j]=fexp(Lh[j]-mx1); sum1+=ah[j];
        }
        sum0+=__shfl_xor_sync(FULL,sum0,1); sum0+=__shfl_xor_sync(FULL,sum0,2);
        sum1+=__shfl_xor_sync(FULL,sum1,1); sum1+=__shfl_xor_sync(FULL,sum1,2);
        float inv0=1.f/sum0, inv1=1.f/sum1;
        float rm0=rs0*m0, rm1=rs1*m1;
#pragma unroll
        for(int j=0;j<4;j++){
            ag[j]*=inv0; ah[j]*=inv1;
            t2p[j]+=ag[j]+ah[j];
            t1p[j]+=ag[j]*rm0+ah[j]*rm1;
        }
        {
            int s0=2*c4;
            sm[wb+g*17+s0]=ag[0];     sm[wb+g*17+s0+1]=ag[1];
            sm[wb+g*17+s0+8]=ag[2];   sm[wb+g*17+s0+9]=ag[3];
            sm[wb+(g+8)*17+s0]=ah[0]; sm[wb+(g+8)*17+s0+1]=ah[1];
            sm[wb+(g+8)*17+s0+8]=ah[2]; sm[wb+(g+8)*17+s0+9]=ah[3];
        }
        __syncwarp();
        if(writeA0){
            int row=l&15, sh=l>>4;
#pragma unroll
            for(int j=0;j<8;j++){
                int slot=j*2+sh;
                a0out[(size_t)b*65536+(size_t)slot*4096+p*512+rb16+row]=sm[wb+row*17+slot];
            }
        }
#pragma unroll
        for(int kc=0;kc<2;kc++){
            int ra=kc*8+c4, rb2=ra+4;
            float rsa=sm[RSTD+rb16+ra], rsb=sm[RSTD+rb16+rb2];
            unsigned A0=tf32r(sm[wb+ra*17+g]*rsa);
            unsigned A1=tf32r(sm[wb+ra*17+g+8]*rsa);
            unsigned A2=tf32r(sm[wb+rb2*17+g]*rsb);
            unsigned A3=tf32r(sm[wb+rb2*17+g+8]*rsb);
            int swa=(c4<<2), swb=((c4+4)<<2);
#pragma unroll
            for(int nt=0;nt<16;nt++){
                int half=nt>>3;
                int chh=(nt&7)*8+g;
                int c16=chh>>2, frac=chh&3;
                unsigned B0=__float_as_uint(sm[wst+half*1024+ra*64+(((c16*4)^swa)+frac)]);
                unsigned B1=__float_as_uint(sm[wst+half*1024+rb2*64+(((c16*4)^swb)+frac)]);
                MMA1688((&sacc[nt*4]),A0,A1,A2,A3,B0,B1);
            }
        }
    }
#pragma unroll
    for(int j=0;j<4;j++){
#pragma unroll
        for(int d=4;d<32;d<<=1){
            t2p[j]+=__shfl_xor_sync(FULL,t2p[j],d);
            t1p[j]+=__shfl_xor_sync(FULL,t1p[j],d);
        }
    }
    if(l<4){
        int s0=2*l;
        atomicAdd(&sm[T2S+s0],t2p[0]);   atomicAdd(&sm[T2S+s0+1],t2p[1]);
        atomicAdd(&sm[T2S+s0+8],t2p[2]); atomicAdd(&sm[T2S+s0+9],t2p[3]);
        atomicAdd(&sm[T1S+s0],t1p[0]);   atomicAdd(&sm[T1S+s0+1],t1p[1]);
        atomicAdd(&sm[T1S+s0+8],t1p[2]); atomicAdd(&sm[T1S+s0+9],t1p[3]);
    }
    __syncthreads();
    for(int i=t;i<2048;i+=256) sm[SBLK+i]=0.f;
    __syncthreads();
#pragma unroll
    for(int nt=0;nt<16;nt++){
        int ch0=nt*8+2*c4;
        atomicAdd(&sm[SBLK+g*128+ch0],sacc[nt*4+0]);
        atomicAdd(&sm[SBLK+g*128+ch0+1],sacc[nt*4+1]);
        atomicAdd(&sm[SBLK+(g+8)*128+ch0],sacc[nt*4+2]);
        atomicAdd(&sm[SBLK+(g+8)*128+ch0+1],sacc[nt*4+3]);
    }
    __syncthreads();
    float* tp=g_Tpart+((size_t)(b*8+p))*2048;
    for(int i=t;i<2048;i+=256) tp[i]=sm[SBLK+i];
    if(t<16){g_t1p[(b*8+p)*16+t]=sm[T1S+t];g_t2p[(b*8+p)*16+t]=sm[T2S+t];}
}

// ---- ktail v2 + unrolled weight walks ----
__global__ void __launch_bounds__(256) ktail2(const float* __restrict__ Wv,
        const float* __restrict__ gkv, const float* __restrict__ bkv,
        const float* __restrict__ wih, const float* __restrict__ whh,
        const float* __restrict__ bih, const float* __restrict__ bhh,
        const float* __restrict__ g2, const float* __restrict__ b2ln,
        const float* __restrict__ w1, const float* __restrict__ b1,
        const float* __restrict__ w2, const float* __restrict__ b2f,
        const float* __restrict__ gq, const float* __restrict__ bq,
        float* __restrict__ qout, int last){
    int blk=blockIdx.x, b=blk>>2, qh=(blk&3)*4;
    int t=threadIdx.x, w=t>>5, l=t&31;
    __shared__ float Sh[4][128], su[4][128], sx[4][128], sy[4][128];
    __shared__ float gg[4][772];
    __shared__ float pu[2][4][128];
    __shared__ float sh1[4][512];
    __shared__ float t1a[4], t2a[4], rsa[4];
    float (*szb)[128] = (float(*)[128])sh1;

    if(t<4){
        float s1=0.f,s2=0.f;
        for(int p=0;p<8;p++){
            s1+=g_t1p[(b*8+p)*16+qh+t];
            s2+=g_t2p[(b*8+p)*16+qh+t];
        }
        t1a[t]=s1; t2a[t]=s2; rsa[t]=1.f/(s2+1e-5f);
    }
#pragma unroll
    for(int k=0;k<2;k++)
        ((float*)sx)[k*256+t]=g_qstate[(b*16+qh)*128+k*256+t];
    __syncthreads();
#pragma unroll
    for(int k=0;k<2;k++){
        int idx=k*256+t, q=idx>>7, c=idx&127;
        float a=0.f;
#pragma unroll
        for(int p=0;p<8;p++) a+=g_Tpart[((size_t)(b*8+p))*2048+(qh+q)*128+c];
        ((float*)Sh)[idx]=fmaf(gkv[c],a-t1a[q],bkv[c]*t2a[q]);
    }
    __syncthreads();
    {
        int c=t&127, h=t>>7;
        float acc[4]={0,0,0,0};
        const float4* wr=(const float4*)(Wv+(size_t)c*128+h*64);
#pragma unroll
        for(int d=0;d<16;d++){
            float4 wv=wr[d];
#pragma unroll
            for(int k=0;k<4;k++) acc[k]+=dot4(((const float4*)(Sh[k]+h*64))[d],wv);
        }
#pragma unroll
        for(int k=0;k<4;k++) pu[h][k][c]=acc[k];
    }
    __syncthreads();
#pragma unroll
    for(int j=0;j<2;j++){
        int i=t+j*256, r=i>>7, c=i&127;
        su[r][c]=(pu[0][r][c]+pu[1][r][c])*rsa[r];
    }
    __syncthreads();
#pragma unroll
    for(int j=0;j<3;j++){
        int o=t+j*256;
        const float* wrow = (o<384) ? (wih+(size_t)o*128) : (whh+(size_t)(o-384)*128);
        const float (*A)[128] = (o<384) ? su : sx;
        const float4* wr=(const float4*)wrow;
        float acc[4]={0,0,0,0};
#pragma unroll 8
        for(int d=0;d<32;d++){
            float4 wv=wr[d];
#pragma unroll
            for(int k=0;k<4;k++) acc[k]+=dot4(((const float4*)A[k])[d],wv);
        }
#pragma unroll
        for(int k=0;k<4;k++) gg[k][o]=acc[k];
    }
    __syncthreads();
#pragma unroll
    for(int j=0;j<2;j++){
        int i=t+j*256, r=i>>7, c=i&127;
        float rr=1.f/(1.f+fexp(-(gg[r][c]+bih[c]+gg[r][384+c]+bhh[c])));
        float zz=1.f/(1.f+fexp(-(gg[r][128+c]+bih[128+c]+gg[r][512+c]+bhh[128+c])));
        float nn=tanhf(gg[r][256+c]+bih[256+c]+rr*(gg[r][640+c]+bhh[256+c]));
        sy[r][c]=(1.f-zz)*nn+zz*sx[r][c];
    }
    __syncthreads();
    if(w<4) ln_row(sy,szb,g2,b2ln,w,l);
    __syncthreads();
    {
        float acc0[4]={0,0,0,0}, acc1[4]={0,0,0,0};
        const float4* wa=(const float4*)(w1+(size_t)t*128);
        const float4* wb2=(const float4*)(w1+(size_t)(t+256)*128);
#pragma unroll 8
        for(int d=0;d<32;d++){
            float4 a=wa[d], bb=wb2[d];
#pragma unroll
            for(int r=0;r<4;r++){
                float4 zz=((const float4*)szb[r])[d];
                acc0[r]+=dot4(zz,a); acc1[r]+=dot4(zz,bb);
            }
        }
        float b0=b1[t], b256=b1[t+256];
        __syncthreads();
#pragma unroll
        for(int r=0;r<4;r++){
            sh1[r][t]=fmaxf(acc0[r]+b0,0.f);
            sh1[r][t+256]=fmaxf(acc1[r]+b256,0.f);
        }
    }
    __syncthreads();
    {
        int c=t&127, h=t>>7;
        float acc[4]={0,0,0,0};
        const float4* wp=(const float4*)(w2+(size_t)c*512+h*256);
#pragma unroll 8
        for(int d=0;d<64;d++){
            float4 wv=wp[d];
#pragma unroll
            for(int k=0;k<4;k++) acc[k]+=dot4(((const float4*)(sh1[k]+h*256))[d],wv);
        }
#pragma unroll
        for(int k=0;k<4;k++) pu[h][k][c]=acc[k];
    }
    __syncthreads();
#pragma unroll
    for(int j=0;j<2;j++){
        int i=t+j*256, r=i>>7, c=i&127;
        float val=sy[r][c]+pu[0][r][c]+pu[1][r][c]+b2f[c];
        g_qstate[(b*16+qh+r)*128+c]=val;
        su[r][c]=val;
        if(last) qout[(b*16+qh+r)*128+c]=val;
    }
    __syncthreads();
    if(last) return;
    if(w<4) ln_row(su,szb,gq,bq,w,l);
    __syncthreads();
    {
        int c=t&127, h=t>>7;
        float acc[4]={0,0,0,0};
#pragma unroll 8
        for(int e=h*64;e<h*64+64;e++){
            float mv=g_M1[e*128+c];
#pragma unroll
            for(int k=0;k<4;k++) acc[k]=fmaf(szb[k][e],mv,acc[k]);
        }
#pragma unroll
        for(int k=0;k<4;k++) pu[h][k][c]=acc[k];
    }
    __syncthreads();
#pragma unroll
    for(int j=0;j<2;j++){
        int i=t+j*256, r=i>>7, c=i&127;
        Sh[r][c]=pu[0][r][c]+pu[1][r][c];
    }
    __syncthreads();
    if(w<4){
        int qbase=b*16+qh;
        float4 qr=((const float4*)Sh[w])[l];
        float4 g4=((const float4*)gkv)[l], b4=((const float4*)bkv)[l];
        float c1=dot4(qr,g4), c0=dot4(qr,b4);
#pragma unroll
        for(int d=16;d>0;d>>=1){c1+=__shfl_xor_sync(FULL,c1,d);c0+=__shfl_xor_sync(FULL,c0,d);}
        if(l==0){g_cq1[qbase+w]=c1; g_cq0[qbase+w]=c0;}
        float4 o; o.x=qr.x*g4.x; o.y=qr.y*g4.y; o.z=qr.z*g4.z; o.w=qr.w*g4.w;
        ((float4*)(g_qkg+(qbase+w)*128))[l]=o;
    }
}

extern "C" void kernel_launch(void* const* d_in, const int* in_sizes, int n_in,
                              void* d_out, int out_size){
    const float* inp=(const float*)d_in[0];
    const float* query=(const float*)d_in[1];
    const float* ln_kv_g=(const float*)d_in[2];
    const float* ln_kv_b=(const float*)d_in[3];
    const float* Wk=(const float*)d_in[4];
    const float* Wv=(const float*)d_in[5];
    const float* ln_q_g=(const float*)d_in[6];
    const float* ln_q_b=(const float*)d_in[7];
    const float* Wq=(const float*)d_in[8];
    const float* gru_wih=(const float*)d_in[9];
    const float* gru_whh=(const float*)d_in[10];
    const float* gru_bih=(const float*)d_in[11];
    const float* gru_bhh=(const float*)d_in[12];
    const float* ln2_g=(const float*)d_in[13];
    const float* ln2_b=(const float*)d_in[14];
    const float* ffn_w1=(const float*)d_in[15];
    const float* ffn_b1=(const float*)d_in[16];
    const float* ffn_w2=(const float*)d_in[17];
    const float* ffn_b2=(const float*)d_in[18];
    float* out=(float*)d_out;
    float* a0out=out+32*16*128;

    int smemB = SMEMF*4;
    cudaFuncSetAttribute(kstream10, cudaFuncAttributeMaxDynamicSharedMemorySize, smemB);
    kM1<<<128,128>>>(Wq,Wk);
    kqk0<<<64,256>>>(query,ln_q_g,ln_q_b,ln_kv_g,ln_kv_b);
    for(int it=0;it<3;it++){
        int last=(it==2);
        kstream10<<<dim3(8,32),256,smemB>>>(inp,a0out,last,it==0);
        ktail2<<<128,256>>>(Wv,ln_kv_g,ln_kv_b,gru_wih,gru_whh,gru_bih,gru_bhh,
                            ln2_g,ln2_b,ffn_w1,ffn_b1,ffn_w2,ffn_b2,
                            ln_q_g,ln_q_b,out,last);
    }
}

// round 15
// speedup vs baseline: 1.0586x; 1.0586x over previous
#include <cuda_runtime.h>
#include <math.h>
#define FULL 0xffffffffu

__device__ float g_M1[128*128];
__device__ float g_qstate[32*16*128];
__device__ float g_qkg[32*16*128];
__device__ float g_cq1[32*16];
__device__ float g_cq0[32*16];
__device__ float g_Tpart[32*8*16*128];
__device__ float g_t1p[32*8*16];
__device__ float g_t2p[32*8*16];
__device__ float g_rstdc[32*4096];
__device__ float g_mc[32*4096];

static __device__ __forceinline__ float dot4(float4 a, float4 b) {
    return fmaf(a.x,b.x,fmaf(a.y,b.y,fmaf(a.z,b.z,a.w*b.w)));
}
static __device__ __forceinline__ unsigned tf32r(float x){
    unsigned u; asm("cvt.rna.tf32.f32 %0, %1;" : "=r"(u) : "f"(x)); return u;
}
#define MMA1688(D,A0,A1,A2,A3,B0,B1) \
  asm volatile("mma.sync.aligned.m16n8k8.row.col.f32.tf32.tf32.f32 " \
    "{%0,%1,%2,%3},{%4,%5,%6,%7},{%8,%9},{%0,%1,%2,%3};" \
    : "+f"(D[0]),"+f"(D[1]),"+f"(D[2]),"+f"(D[3]) \
    : "r"(A0),"r"(A1),"r"(A2),"r"(A3),"r"(B0),"r"(B1))

static __device__ __forceinline__ float fexp(float x) {
    x = fmaxf(x, -87.f);
    float t = fmaf(x, 1.4426950408889634f, 12582912.f);
    int ni = __float_as_int(t) - 0x4B400000;
    float n = t - 12582912.f;
    float f = fmaf(x, 1.4426950408889634f, -n);
    float p = 1.5403530e-4f;
    p = fmaf(p,f,1.3333558e-3f); p = fmaf(p,f,9.6181291e-3f);
    p = fmaf(p,f,5.5504109e-2f); p = fmaf(p,f,2.4022651e-1f);
    p = fmaf(p,f,6.9314718e-1f); p = fmaf(p,f,1.f);
    return p * __int_as_float((ni + 127) << 23);
}

__global__ void kM1(const float* __restrict__ Wq, const float* __restrict__ Wk){
    __shared__ float wq[128];
    int e=blockIdx.x, d=threadIdx.x;
    wq[d]=Wq[d*128+e];
    __syncthreads();
    float a=0.f;
#pragma unroll 8
    for(int c=0;c<128;c++) a=fmaf(wq[c],Wk[c*128+d],a);
    g_M1[e*128+d]=a*0.08838834764831845f;
}

static __device__ __forceinline__ void ln_row(const float (*sq)[128], float (*sz)[128],
        const float* gq, const float* bq, int w, int l){
    float4 y4=((const float4*)sq[w])[l];
    float s=y4.x+y4.y+y4.z+y4.w;
    float s2=fmaf(y4.x,y4.x,fmaf(y4.y,y4.y,fmaf(y4.z,y4.z,y4.w*y4.w)));
#pragma unroll
    for(int d=16;d>0;d>>=1){s+=__shfl_xor_sync(FULL,s,d);s2+=__shfl_xor_sync(FULL,s2,d);}
    float m=s*(1.f/128.f);
    float rstd=rsqrtf(fmaf(s2,1.f/128.f,-m*m)+1e-5f);
    float4 gg=((const float4*)gq)[l], bb=((const float4*)bq)[l];
    float4 z4;
    z4.x=fmaf((y4.x-m)*rstd,gg.x,bb.x); z4.y=fmaf((y4.y-m)*rstd,gg.y,bb.y);
    z4.z=fmaf((y4.z-m)*rstd,gg.z,bb.z); z4.w=fmaf((y4.w-m)*rstd,gg.w,bb.w);
    ((float4*)sz[w])[l]=z4;
}

template<int NR>
static __device__ __forceinline__ void qkproj(const float (*sz)[128], float (*qkraw)[128],
        const float* gkv, const float* bkv, int qbase, int t, int w, int l){
    const int RG=NR/2;
    int c=t&127, rq=(t>>7)*RG;
    float acc[RG];
#pragma unroll
    for(int k=0;k<RG;k++) acc[k]=0.f;
    for(int e=0;e<128;e++){
        float mv=g_M1[e*128+c];
#pragma unroll
        for(int k=0;k<RG;k++) acc[k]=fmaf(sz[rq+k][e],mv,acc[k]);
    }
#pragma unroll
    for(int k=0;k<RG;k++) qkraw[rq+k][c]=acc[k];
    __syncthreads();
    if(w<NR){
        float4 qr=((const float4*)qkraw[w])[l];
        float4 g4=((const float4*)gkv)[l], b4=((const float4*)bkv)[l];
        float c1=dot4(qr,g4), c0=dot4(qr,b4);
#pragma unroll
        for(int d=16;d>0;d>>=1){c1+=__shfl_xor_sync(FULL,c1,d);c0+=__shfl_xor_sync(FULL,c0,d);}
        if(l==0){g_cq1[qbase+w]=c1; g_cq0[qbase+w]=c0;}
        float4 o; o.x=qr.x*g4.x; o.y=qr.y*g4.y; o.z=qr.z*g4.z; o.w=qr.w*g4.w;
        ((float4*)(g_qkg+(qbase+w)*128))[l]=o;
    }
}

__global__ void __launch_bounds__(256) kqk0(const float* __restrict__ query,
        const float* __restrict__ gq,
        const float* __restrict__ bq, const float* __restrict__ gkv,
        const float* __restrict__ bkv){
    int qbase=blockIdx.x*8, t=threadIdx.x, w=t>>5, l=t&31;
    __shared__ float sq[8][128], sz[8][128], qkraw[8][128];
#pragma unroll
    for(int k=0;k<4;k++){
        float v=query[qbase*128+k*256+t];
        ((float*)sq)[k*256+t]=v;
        g_qstate[qbase*128+k*256+t]=v;
    }
    __syncthreads();
    ln_row(sq,sz,gq,bq,w,l);
    __syncthreads();
    qkproj<8>(sz,qkraw,gkv,bkv,qbase,t,w,l);
}

#define STG0 0
#define QKF  16384
#define WBUF 18432
#define RSTD 20608
#define MS   21120
#define SBLK 21632
#define T1S  23680
#define T2S  23696
#define CQ1S 23712
#define CQ0S 23728
#define SMEMF 23744

// ---- single-pass stream: dual phase-1 accumulator chains ----
__global__ void __launch_bounds__(256,2) kstream11(const float* __restrict__ inp,
        float* __restrict__ a0out, int writeA0, int iter0){
    extern __shared__ float sm[];
    int p=blockIdx.x, b=blockIdx.y, t=threadIdx.x, w=t>>5, l=t&31;
    int g=l>>2, c4=l&3;
    if(t<16){
        sm[T1S+t]=0.f; sm[T2S+t]=0.f;
        sm[CQ1S+t]=g_cq1[b*16+t]; sm[CQ0S+t]=g_cq0[b*16+t];
    }
#pragma unroll
    for(int e=0;e<8;e++){
        int gi=e*256+t;
        int j=gi&1, nt=(gi>>1)&1, lane=(gi>>2)&31, k=gi>>7;
        int slot=nt*8+(lane>>2), ch=k*8+(lane&3)+j*4;
        sm[QKF+gi]=__uint_as_float(tf32r(g_qkg[b*2048+slot*128+ch]));
    }
    if(!iter0){
#pragma unroll
        for(int k=0;k<2;k++){
            sm[RSTD+k*256+t]=g_rstdc[b*4096+p*512+k*256+t];
            sm[MS+k*256+t]=g_mc[b*4096+p*512+k*256+t];
        }
    }
    __syncthreads();
    int rb=w*64;
    if(iter0){
        const float4* base=(const float4*)(inp+((size_t)b*4096+p*512+rb)*128);
        for(int i=0;i<64;i++){
            float4 x=base[i*32+l];
            float s=x.x+x.y+x.z+x.w;
            float s2=fmaf(x.x,x.x,fmaf(x.y,x.y,fmaf(x.z,x.z,x.w*x.w)));
#pragma unroll
            for(int d=16;d>0;d>>=1){s+=__shfl_xor_sync(FULL,s,d);s2+=__shfl_xor_sync(FULL,s2,d);}
            float m=s*(1.f/128.f);
            float rs=rsqrtf(fmaf(s2,1.f/128.f,-m*m)+1e-5f);
            if(l==0){sm[RSTD+rb+i]=rs;sm[MS+rb+i]=m;}
        }
        __syncthreads();
#pragma unroll
        for(int k=0;k<2;k++){
            g_rstdc[b*4096+p*512+k*256+t]=sm[RSTD+k*256+t];
            g_mc[b*4096+p*512+k*256+t]=sm[MS+k*256+t];
        }
    }
    float cq1v[4], cq0v[4];
    {
        int s0=2*c4;
        cq1v[0]=sm[CQ1S+s0];   cq1v[1]=sm[CQ1S+s0+1];
        cq1v[2]=sm[CQ1S+s0+8]; cq1v[3]=sm[CQ1S+s0+9];
        cq0v[0]=sm[CQ0S+s0];   cq0v[1]=sm[CQ0S+s0+1];
        cq0v[2]=sm[CQ0S+s0+8]; cq0v[3]=sm[CQ0S+s0+9];
    }
    float sacc[64];
#pragma unroll
    for(int i=0;i<64;i++) sacc[i]=0.f;
    float t1p[4]={0,0,0,0}, t2p[4]={0,0,0,0};
    int wst=STG0+w*2048;
    int wb=WBUF+w*272;

    for(int tile=0;tile<4;tile++){
        __syncwarp();
        int rb16=rb+tile*16;
        const float4* gsrc=(const float4*)(inp+((size_t)b*4096+p*512+rb16)*128);
#pragma unroll
        for(int half=0;half<2;half++){
#pragma unroll
            for(int ii=0;ii<8;ii++){
                int row=ii*2+(l>>4);
                const float4* src=gsrc+row*32+half*16+(l&15);
                unsigned dst=(unsigned)__cvta_generic_to_shared(
                    sm+wst+half*1024+row*64+(((l&15)*4)^((row&7)<<2)));
                asm volatile("cp.async.cg.shared.global [%0], [%1], 16;\n"
                             ::"r"(dst),"l"(src):"memory");
            }
        }
        asm volatile("cp.async.commit_group;\n":::"memory");
        asm volatile("cp.async.wait_group 0;\n":::"memory");
        __syncwarp();
        // phase 1: logits MMA with TWO independent accumulator chains
        float d0a[4]={0,0,0,0}, d1a[4]={0,0,0,0};
        float d0b[4]={0,0,0,0}, d1b[4]={0,0,0,0};
        int abase=wst+g*64;
#pragma unroll
        for(int kk=0;kk<8;kk++){
            {   // chain A: k = kk (half 0)
                int x0=((kk*8)+c4)^(g<<2);
                unsigned a0=__float_as_uint(sm[abase+x0]);
                unsigned a1=__float_as_uint(sm[abase+512+x0]);
                unsigned a2=__float_as_uint(sm[abase+(x0^4)]);
                unsigned a3=__float_as_uint(sm[abase+512+(x0^4)]);
                float4 bv=*(const float4*)&sm[QKF+kk*128+l*4];
                MMA1688(d0a,a0,a1,a2,a3,__float_as_uint(bv.x),__float_as_uint(bv.y));
                MMA1688(d1a,a0,a1,a2,a3,__float_as_uint(bv.z),__float_as_uint(bv.w));
            }
            {   // chain B: k = kk+8 (half 1)
                int ab=abase+1024;
                int x0=((kk*8)+c4)^(g<<2);
                unsigned a0=__float_as_uint(sm[ab+x0]);
                unsigned a1=__float_as_uint(sm[ab+512+x0]);
                unsigned a2=__float_as_uint(sm[ab+(x0^4)]);
                unsigned a3=__float_as_uint(sm[ab+512+(x0^4)]);
                float4 bv=*(const float4*)&sm[QKF+(kk+8)*128+l*4];
                MMA1688(d0b,a0,a1,a2,a3,__float_as_uint(bv.x),__float_as_uint(bv.y));
                MMA1688(d1b,a0,a1,a2,a3,__float_as_uint(bv.z),__float_as_uint(bv.w));
            }
        }
        float d0[4], d1[4];
#pragma unroll
        for(int i=0;i<4;i++){ d0[i]=d0a[i]+d0b[i]; d1[i]=d1a[i]+d1b[i]; }
        int r0g=rb16+g, r1g=r0g+8;
        float rs0=sm[RSTD+r0g], m0=sm[MS+r0g];
        float rs1=sm[RSTD+r1g], m1=sm[MS+r1g];
        float Lg[4], Lh[4];
        Lg[0]=fmaf(rs0,fmaf(-m0,cq1v[0],d0[0]),cq0v[0]);
        Lg[1]=fmaf(rs0,fmaf(-m0,cq1v[1],d0[1]),cq0v[1]);
        Lg[2]=fmaf(rs0,fmaf(-m0,cq1v[2],d1[0]),cq0v[2]);
        Lg[3]=fmaf(rs0,fmaf(-m0,cq1v[3],d1[1]),cq0v[3]);
        Lh[0]=fmaf(rs1,fmaf(-m1,cq1v[0],d0[2]),cq0v[0]);
        Lh[1]=fmaf(rs1,fmaf(-m1,cq1v[1],d0[3]),cq0v[1]);
        Lh[2]=fmaf(rs1,fmaf(-m1,cq1v[2],d1[2]),cq0v[2]);
        Lh[3]=fmaf(rs1,fmaf(-m1,cq1v[3],d1[3]),cq0v[3]);
        float mx0=fmaxf(fmaxf(Lg[0],Lg[1]),fmaxf(Lg[2],Lg[3]));
        float mx1=fmaxf(fmaxf(Lh[0],Lh[1]),fmaxf(Lh[2],Lh[3]));
        mx0=fmaxf(mx0,__shfl_xor_sync(FULL,mx0,1));
        mx0=fmaxf(mx0,__shfl_xor_sync(FULL,mx0,2));
        mx1=fmaxf(mx1,__shfl_xor_sync(FULL,mx1,1));
        mx1=fmaxf(mx1,__shfl_xor_sync(FULL,mx1,2));
        float ag[4], ah[4], sum0=0.f, sum1=0.f;
#pragma unroll
        for(int j=0;j<4;j++){
            ag[j]=fexp(Lg[j]-mx0); sum0+=ag[j];
            ah[j]=fexp(Lh[j]-mx1); sum1+=ah[j];
        }
        sum0+=__shfl_xor_sync(FULL,sum0,1); sum0+=__shfl_xor_sync(FULL,sum0,2);
        sum1+=__shfl_xor_sync(FULL,sum1,1); sum1+=__shfl_xor_sync(FULL,sum1,2);
        float inv0=1.f/sum0, inv1=1.f/sum1;
        float rm0=rs0*m0, rm1=rs1*m1;
#pragma unroll
        for(int j=0;j<4;j++){
            ag[j]*=inv0; ah[j]*=inv1;
            t2p[j]+=ag[j]+ah[j];
            t1p[j]+=ag[j]*rm0+ah[j]*rm1;
        }
        {
            int s0=2*c4;
            sm[wb+g*17+s0]=ag[0];     sm[wb+g*17+s0+1]=ag[1];
            sm[wb+g*17+s0+8]=ag[2];   sm[wb+g*17+s0+9]=ag[3];
            sm[wb+(g+8)*17+s0]=ah[0]; sm[wb+(g+8)*17+s0+1]=ah[1];
            sm[wb+(g+8)*17+s0+8]=ah[2]; sm[wb+(g+8)*17+s0+9]=ah[3];
        }
        __syncwarp();
        if(writeA0){
            int row=l&15, sh=l>>4;
#pragma unroll
            for(int j=0;j<8;j++){
                int slot=j*2+sh;
                a0out[(size_t)b*65536+(size_t)slot*4096+p*512+rb16+row]=sm[wb+row*17+slot];
            }
        }
#pragma unroll
        for(int kc=0;kc<2;kc++){
            int ra=kc*8+c4, rb2=ra+4;
            float rsa=sm[RSTD+rb16+ra], rsb=sm[RSTD+rb16+rb2];
            unsigned A0=tf32r(sm[wb+ra*17+g]*rsa);
            unsigned A1=tf32r(sm[wb+ra*17+g+8]*rsa);
            unsigned A2=tf32r(sm[wb+rb2*17+g]*rsb);
            unsigned A3=tf32r(sm[wb+rb2*17+g+8]*rsb);
            int swa=(c4<<2), swb=((c4+4)<<2);
#pragma unroll
            for(int nt=0;nt<16;nt++){
                int half=nt>>3;
                int chh=(nt&7)*8+g;
                int c16=chh>>2, frac=chh&3;
                unsigned B0=__float_as_uint(sm[wst+half*1024+ra*64+(((c16*4)^swa)+frac)]);
                unsigned B1=__float_as_uint(sm[wst+half*1024+rb2*64+(((c16*4)^swb)+frac)]);
                MMA1688((&sacc[nt*4]),A0,A1,A2,A3,B0,B1);
            }
        }
    }
#pragma unroll
    for(int j=0;j<4;j++){
#pragma unroll
        for(int d=4;d<32;d<<=1){
            t2p[j]+=__shfl_xor_sync(FULL,t2p[j],d);
            t1p[j]+=__shfl_xor_sync(FULL,t1p[j],d);
        }
    }
    if(l<4){
        int s0=2*l;
        atomicAdd(&sm[T2S+s0],t2p[0]);   atomicAdd(&sm[T2S+s0+1],t2p[1]);
        atomicAdd(&sm[T2S+s0+8],t2p[2]); atomicAdd(&sm[T2S+s0+9],t2p[3]);
        atomicAdd(&sm[T1S+s0],t1p[0]);   atomicAdd(&sm[T1S+s0+1],t1p[1]);
        atomicAdd(&sm[T1S+s0+8],t1p[2]); atomicAdd(&sm[T1S+s0+9],t1p[3]);
    }
    __syncthreads();
    for(int i=t;i<2048;i+=256) sm[SBLK+i]=0.f;
    __syncthreads();
#pragma unroll
    for(int nt=0;nt<16;nt++){
        int ch0=nt*8+2*c4;
        atomicAdd(&sm[SBLK+g*128+ch0],sacc[nt*4+0]);
        atomicAdd(&sm[SBLK+g*128+ch0+1],sacc[nt*4+1]);
        atomicAdd(&sm[SBLK+(g+8)*128+ch0],sacc[nt*4+2]);
        atomicAdd(&sm[SBLK+(g+8)*128+ch0+1],sacc[nt*4+3]);
    }
    __syncthreads();
    float* tp=g_Tpart+((size_t)(b*8+p))*2048;
    for(int i=t;i<2048;i+=256) tp[i]=sm[SBLK+i];
    if(t<16){g_t1p[(b*8+p)*16+t]=sm[T1S+t];g_t2p[(b*8+p)*16+t]=sm[T2S+t];}
}

// ---- ktail v2 (byte-identical R13) ----
__global__ void __launch_bounds__(256) ktail2(const float* __restrict__ Wv,
        const float* __restrict__ gkv, const float* __restrict__ bkv,
        const float* __restrict__ wih, const float* __restrict__ whh,
        const float* __restrict__ bih, const float* __restrict__ bhh,
        const float* __restrict__ g2, const float* __restrict__ b2ln,
        const float* __restrict__ w1, const float* __restrict__ b1,
        const float* __restrict__ w2, const float* __restrict__ b2f,
        const float* __restrict__ gq, const float* __restrict__ bq,
        float* __restrict__ qout, int last){
    int blk=blockIdx.x, b=blk>>2, qh=(blk&3)*4;
    int t=threadIdx.x, w=t>>5, l=t&31;
    __shared__ float Sh[4][128], su[4][128], sx[4][128], sy[4][128];
    __shared__ float gg[4][772];
    __shared__ float pu[2][4][128];
    __shared__ float sh1[4][512];
    __shared__ float t1a[4], t2a[4], rsa[4];
    float (*szb)[128] = (float(*)[128])sh1;

    if(t<4){
        float s1=0.f,s2=0.f;
        for(int p=0;p<8;p++){
            s1+=g_t1p[(b*8+p)*16+qh+t];
            s2+=g_t2p[(b*8+p)*16+qh+t];
        }
        t1a[t]=s1; t2a[t]=s2; rsa[t]=1.f/(s2+1e-5f);
    }
#pragma unroll
    for(int k=0;k<2;k++)
        ((float*)sx)[k*256+t]=g_qstate[(b*16+qh)*128+k*256+t];
    __syncthreads();
#pragma unroll
    for(int k=0;k<2;k++){
        int idx=k*256+t, q=idx>>7, c=idx&127;
        float a=0.f;
        for(int p=0;p<8;p++) a+=g_Tpart[((size_t)(b*8+p))*2048+(qh+q)*128+c];
        ((float*)Sh)[idx]=fmaf(gkv[c],a-t1a[q],bkv[c]*t2a[q]);
    }
    __syncthreads();
    {
        int c=t&127, h=t>>7;
        float acc[4]={0,0,0,0};
        const float4* wr=(const float4*)(Wv+(size_t)c*128+h*64);
        for(int d=0;d<16;d++){
            float4 wv=wr[d];
#pragma unroll
            for(int k=0;k<4;k++) acc[k]+=dot4(((const float4*)(Sh[k]+h*64))[d],wv);
        }
#pragma unroll
        for(int k=0;k<4;k++) pu[h][k][c]=acc[k];
    }
    __syncthreads();
#pragma unroll
    for(int j=0;j<2;j++){
        int i=t+j*256, r=i>>7, c=i&127;
        su[r][c]=(pu[0][r][c]+pu[1][r][c])*rsa[r];
    }
    __syncthreads();
#pragma unroll
    for(int j=0;j<3;j++){
        int o=t+j*256;
        const float* wrow = (o<384) ? (wih+(size_t)o*128) : (whh+(size_t)(o-384)*128);
        const float (*A)[128] = (o<384) ? su : sx;
        const float4* wr=(const float4*)wrow;
        float acc[4]={0,0,0,0};
        for(int d=0;d<32;d++){
            float4 wv=wr[d];
#pragma unroll
            for(int k=0;k<4;k++) acc[k]+=dot4(((const float4*)A[k])[d],wv);
        }
#pragma unroll
        for(int k=0;k<4;k++) gg[k][o]=acc[k];
    }
    __syncthreads();
#pragma unroll
    for(int j=0;j<2;j++){
        int i=t+j*256, r=i>>7, c=i&127;
        float rr=1.f/(1.f+fexp(-(gg[r][c]+bih[c]+gg[r][384+c]+bhh[c])));
        float zz=1.f/(1.f+fexp(-(gg[r][128+c]+bih[128+c]+gg[r][512+c]+bhh[128+c])));
        float nn=tanhf(gg[r][256+c]+bih[256+c]+rr*(gg[r][640+c]+bhh[256+c]));
        sy[r][c]=(1.f-zz)*nn+zz*sx[r][c];
    }
    __syncthreads();
    if(w<4) ln_row(sy,szb,g2,b2ln,w,l);
    __syncthreads();
    {
        float acc0[4]={0,0,0,0}, acc1[4]={0,0,0,0};
        const float4* wa=(const float4*)(w1+(size_t)t*128);
        const float4* wb2=(const float4*)(w1+(size_t)(t+256)*128);
        for(int d=0;d<32;d++){
            float4 a=wa[d], bb=wb2[d];
#pragma unroll
            for(int r=0;r<4;r++){
                float4 zz=((const float4*)szb[r])[d];
                acc0[r]+=dot4(zz,a); acc1[r]+=dot4(zz,bb);
            }
        }
        float b0=b1[t], b256=b1[t+256];
        __syncthreads();
#pragma unroll
        for(int r=0;r<4;r++){
            sh1[r][t]=fmaxf(acc0[r]+b0,0.f);
            sh1[r][t+256]=fmaxf(acc1[r]+b256,0.f);
        }
    }
    __syncthreads();
    {
        int c=t&127, h=t>>7;
        float acc[4]={0,0,0,0};
        const float4* wp=(const float4*)(w2+(size_t)c*512+h*256);
        for(int d=0;d<64;d++){
            float4 wv=wp[d];
#pragma unroll
            for(int k=0;k<4;k++) acc[k]+=dot4(((const float4*)(sh1[k]+h*256))[d],wv);
        }
#pragma unroll
        for(int k=0;k<4;k++) pu[h][k][c]=acc[k];
    }
    __syncthreads();
#pragma unroll
    for(int j=0;j<2;j++){
        int i=t+j*256, r=i>>7, c=i&127;
        float val=sy[r][c]+pu[0][r][c]+pu[1][r][c]+b2f[c];
        g_qstate[(b*16+qh+r)*128+c]=val;
        su[r][c]=val;
        if(last) qout[(b*16+qh+r)*128+c]=val;
    }
    __syncthreads();
    if(last) return;
    if(w<4) ln_row(su,szb,gq,bq,w,l);
    __syncthreads();
    {
        int c=t&127, h=t>>7;
        float acc[4]={0,0,0,0};
        for(int e=h*64;e<h*64+64;e++){
            float mv=g_M1[e*128+c];
#pragma unroll
            for(int k=0;k<4;k++) acc[k]=fmaf(szb[k][e],mv,acc[k]);
        }
#pragma unroll
        for(int k=0;k<4;k++) pu[h][k][c]=acc[k];
    }
    __syncthreads();
#pragma unroll
    for(int j=0;j<2;j++){
        int i=t+j*256, r=i>>7, c=i&127;
        Sh[r][c]=pu[0][r][c]+pu[1][r][c];
    }
    __syncthreads();
    if(w<4){
        int qbase=b*16+qh;
        float4 qr=((const float4*)Sh[w])[l];
        float4 g4=((const float4*)gkv)[l], b4=((const float4*)bkv)[l];
        float c1=dot4(qr,g4), c0=dot4(qr,b4);
#pragma unroll
        for(int d=16;d>0;d>>=1){c1+=__shfl_xor_sync(FULL,c1,d);c0+=__shfl_xor_sync(FULL,c0,d);}
        if(l==0){g_cq1[qbase+w]=c1; g_cq0[qbase+w]=c0;}
        float4 o; o.x=qr.x*g4.x; o.y=qr.y*g4.y; o.z=qr.z*g4.z; o.w=qr.w*g4.w;
        ((float4*)(g_qkg+(qbase+w)*128))[l]=o;
    }
}

extern "C" void kernel_launch(void* const* d_in, const int* in_sizes, int n_in,
                              void* d_out, int out_size){
    const float* inp=(const float*)d_in[0];
    const float* query=(const float*)d_in[1];
    const float* ln_kv_g=(const float*)d_in[2];
    const float* ln_kv_b=(const float*)d_in[3];
    const float* Wk=(const float*)d_in[4];
    const float* Wv=(const float*)d_in[5];
    const float* ln_q_g=(const float*)d_in[6];
    const float* ln_q_b=(const float*)d_in[7];
    const float* Wq=(const float*)d_in[8];
    const float* gru_wih=(const float*)d_in[9];
    const float* gru_whh=(const float*)d_in[10];
    const float* gru_bih=(const float*)d_in[11];
    const float* gru_bhh=(const float*)d_in[12];
    const float* ln2_g=(const float*)d_in[13];
    const float* ln2_b=(const float*)d_in[14];
    const float* ffn_w1=(const float*)d_in[15];
    const float* ffn_b1=(const float*)d_in[16];
    const float* ffn_w2=(const float*)d_in[17];
    const float* ffn_b2=(const float*)d_in[18];
    float* out=(float*)d_out;
    float* a0out=out+32*16*128;

    int smemB = SMEMF*4;
    cudaFuncSetAttribute(kstream11, cudaFuncAttributeMaxDynamicSharedMemorySize, smemB);
    kM1<<<128,128>>>(Wq,Wk);
    kqk0<<<64,256>>>(query,ln_q_g,ln_q_b,ln_kv_g,ln_kv_b);
    for(int it=0;it<3;it++){
        int last=(it==2);
        kstream11<<<dim3(8,32),256,smemB>>>(inp,a0out,last,it==0);
        ktail2<<<128,256>>>(Wv,ln_kv_g,ln_kv_b,gru_wih,gru_whh,gru_bih,gru_bhh,
                            ln2_g,ln2_b,ffn_w1,ffn_b1,ffn_w2,ffn_b2,
                            ln_q_g,ln_q_b,out,last);
    }
}